// round 1
// baseline (speedup 1.0000x reference)
#include <cuda_runtime.h>
#include <cstdint>

#define B_      8
#define Q_      2048
#define DIM_    256
#define NH      8
#define HD      32
#define DFF     1024
#define LEN_IN_ 13294
#define BQ      (B_*Q_)
#define MV      (B_*LEN_IN_)   // 106352 rows of the value GEMM

// ---------------- scratch (static device arrays; no allocation) ----------------
__device__ float g_qp[BQ*DIM_];            // LN1(input)+pos
__device__ float g_value[MV*DIM_];         // source @ Wv + bv   (109 MB)
__device__ float g_off[BQ*DIM_];           // offset projections
__device__ float g_attn[BQ*128];           // attn logits -> probs (in place)
__device__ float g_attnout[BQ*DIM_];       // sampled attention output
__device__ float g_x[BQ*DIM_];             // residual 1
__device__ float g_y[BQ*DIM_];             // LN2 output
__device__ float g_ffn[BQ*DFF];            // FFN hidden

// ---------------- LayerNorm (+ optional additive term) ----------------
__global__ __launch_bounds__(256) void ln_kernel(
    const float* __restrict__ x, const float* __restrict__ g,
    const float* __restrict__ b, const float* __restrict__ addend,
    float* __restrict__ out)
{
    __shared__ float sbuf[8];
    const int row = blockIdx.x;
    const int t = threadIdx.x;
    const float v = x[(size_t)row*DIM_ + t];

    float s = v;
    #pragma unroll
    for (int o = 16; o; o >>= 1) s += __shfl_xor_sync(0xffffffffu, s, o);
    if ((t & 31) == 0) sbuf[t >> 5] = s;
    __syncthreads();
    float mean = 0.f;
    #pragma unroll
    for (int i = 0; i < 8; i++) mean += sbuf[i];
    mean *= (1.f/256.f);

    const float d = v - mean;
    float s2 = d*d;
    #pragma unroll
    for (int o = 16; o; o >>= 1) s2 += __shfl_xor_sync(0xffffffffu, s2, o);
    __syncthreads();
    if ((t & 31) == 0) sbuf[t >> 5] = s2;
    __syncthreads();
    float var = 0.f;
    #pragma unroll
    for (int i = 0; i < 8; i++) var += sbuf[i];
    var *= (1.f/256.f);

    float r = d * rsqrtf(var + 1e-5f) * g[t] + b[t];
    if (addend) r += addend[(size_t)row*DIM_ + t];
    out[(size_t)row*DIM_ + t] = r;
}

// ---------------- generic fp32 GEMM: C = act(A@B + bias) [+resid] [mask-zero rows] ----------------
// A: [M,K] row-major, B: [K,N] row-major. N % 128 == 0, K % 8 == 0. M guarded.
__global__ __launch_bounds__(256) void gemm_kernel(
    const float* __restrict__ A, const float* __restrict__ Bm,
    const float* __restrict__ bias, const float* __restrict__ resid,
    const uint8_t* __restrict__ mask, float* __restrict__ C,
    int M, int N, int K, int relu)
{
    __shared__ float As[8][128];
    __shared__ float Bs[8][128];
    const int tid = threadIdx.x;
    const int tx = tid & 15;
    const int ty = tid >> 4;
    const int row0 = blockIdx.y * 128;
    const int col0 = blockIdx.x * 128;
    const int a_row = tid >> 1;
    const int a_col = (tid & 1) << 2;
    const int b_row = tid >> 5;
    const int b_col = (tid & 31) << 2;

    float acc[8][8];
    #pragma unroll
    for (int i = 0; i < 8; i++)
        #pragma unroll
        for (int j = 0; j < 8; j++) acc[i][j] = 0.f;

    for (int k0 = 0; k0 < K; k0 += 8) {
        float4 av = make_float4(0.f, 0.f, 0.f, 0.f);
        if (row0 + a_row < M)
            av = *(const float4*)(A + (size_t)(row0 + a_row) * K + k0 + a_col);
        As[a_col+0][a_row] = av.x;
        As[a_col+1][a_row] = av.y;
        As[a_col+2][a_row] = av.z;
        As[a_col+3][a_row] = av.w;
        *(float4*)&Bs[b_row][b_col] =
            *(const float4*)(Bm + (size_t)(k0 + b_row) * N + col0 + b_col);
        __syncthreads();
        #pragma unroll
        for (int kk = 0; kk < 8; kk++) {
            float ra[8], rb[8];
            #pragma unroll
            for (int i = 0; i < 8; i++) ra[i] = As[kk][ty*8 + i];
            #pragma unroll
            for (int j = 0; j < 8; j++) rb[j] = Bs[kk][tx*8 + j];
            #pragma unroll
            for (int i = 0; i < 8; i++)
                #pragma unroll
                for (int j = 0; j < 8; j++)
                    acc[i][j] = fmaf(ra[i], rb[j], acc[i][j]);
        }
        __syncthreads();
    }

    #pragma unroll
    for (int i = 0; i < 8; i++) {
        const int r = row0 + ty*8 + i;
        if (r >= M) continue;
        const float mz = (mask && mask[r]) ? 0.f : 1.f;
        #pragma unroll
        for (int j = 0; j < 8; j += 4) {
            const int c = col0 + tx*8 + j;
            float v0 = acc[i][j+0] + bias[c+0];
            float v1 = acc[i][j+1] + bias[c+1];
            float v2 = acc[i][j+2] + bias[c+2];
            float v3 = acc[i][j+3] + bias[c+3];
            if (relu) {
                v0 = fmaxf(v0, 0.f); v1 = fmaxf(v1, 0.f);
                v2 = fmaxf(v2, 0.f); v3 = fmaxf(v3, 0.f);
            }
            if (resid) {
                const float* rp = resid + (size_t)r*N + c;
                v0 += rp[0]; v1 += rp[1]; v2 += rp[2]; v3 += rp[3];
            }
            float4 vv = make_float4(v0*mz, v1*mz, v2*mz, v3*mz);
            *(float4*)(C + (size_t)r*N + c) = vv;
        }
    }
}

// ---------------- softmax over 16 points per (b,q,head) ----------------
__global__ __launch_bounds__(256) void softmax_kernel(float* __restrict__ attn)
{
    const int i = blockIdx.x * blockDim.x + threadIdx.x;   // (bq*8 + h)
    if (i >= BQ*NH) return;
    float* p = attn + (size_t)i * 16;
    float m = p[0];
    #pragma unroll
    for (int k = 1; k < 16; k++) m = fmaxf(m, p[k]);
    float e[16]; float s = 0.f;
    #pragma unroll
    for (int k = 0; k < 16; k++) { e[k] = __expf(p[k] - m); s += e[k]; }
    const float inv = 1.f / s;
    #pragma unroll
    for (int k = 0; k < 16; k++) p[k] = e[k] * inv;
}

// ---------------- loc = ref + off / normalizer ----------------
__global__ __launch_bounds__(256) void loc_kernel(
    const float* __restrict__ ref, const float* __restrict__ off,
    float* __restrict__ loc)
{
    const int idx = blockIdx.x * blockDim.x + threadIdx.x;
    if (idx >= BQ*256) return;
    const int c  = idx & 1;
    const int l  = (idx >> 3) & 3;
    const int bq = idx >> 8;
    const float nd[4] = {100.f, 50.f, 25.f, 13.f};  // square levels: W == H
    const float r = ref[((size_t)bq*4 + l)*2 + c];
    loc[idx] = r + off[idx] / nd[l];
}

// ---------------- MS-deformable bilinear sampling ----------------
// block = one (b,q); warp = head; lane = head_dim channel.
__global__ __launch_bounds__(256) void sample_kernel(
    const float* __restrict__ value, const float* __restrict__ loc,
    const float* __restrict__ attn, float* __restrict__ out)
{
    const int bq   = blockIdx.x;
    const int h    = threadIdx.x >> 5;
    const int lane = threadIdx.x & 31;
    const int b    = bq >> 11;           // / Q_
    const float* locp = loc  + (size_t)bq*256 + h*32;
    const float* ap   = attn + (size_t)bq*128 + h*16;

    constexpr int LH[4] = {100, 50, 25, 13};
    constexpr int LS[4] = {0, 10000, 12500, 13125};

    float acc = 0.f;
    #pragma unroll
    for (int l = 0; l < 4; l++) {
        const int Hh = LH[l], Ww = LH[l];
        const float* vb = value + ((size_t)b*LEN_IN_ + LS[l])*DIM_ + h*32 + lane;
        #pragma unroll
        for (int p = 0; p < 4; p++) {
            const float lx = locp[(l*4 + p)*2 + 0];
            const float ly = locp[(l*4 + p)*2 + 1];
            const float a  = ap[l*4 + p];
            const float x = lx * (float)Ww - 0.5f;
            const float y = ly * (float)Hh - 0.5f;
            const float x0f = floorf(x), y0f = floorf(y);
            const float wx = x - x0f, wy = y - y0f;
            const int x0 = (int)x0f, y0 = (int)y0f;
            const int x1 = x0 + 1,  y1 = y0 + 1;

            const float vx0 = (x0 >= 0 && x0 < Ww) ? 1.f : 0.f;
            const float vx1 = (x1 >= 0 && x1 < Ww) ? 1.f : 0.f;
            const float vy0 = (y0 >= 0 && y0 < Hh) ? 1.f : 0.f;
            const float vy1 = (y1 >= 0 && y1 < Hh) ? 1.f : 0.f;
            const int cx0 = min(max(x0, 0), Ww-1);
            const int cx1 = min(max(x1, 0), Ww-1);
            const int cy0 = min(max(y0, 0), Hh-1);
            const int cy1 = min(max(y1, 0), Hh-1);

            const float g00 = vb[(size_t)(cy0*Ww + cx0)*DIM_] * (vx0*vy0);
            const float g01 = vb[(size_t)(cy0*Ww + cx1)*DIM_] * (vx1*vy0);
            const float g10 = vb[(size_t)(cy1*Ww + cx0)*DIM_] * (vx0*vy1);
            const float g11 = vb[(size_t)(cy1*Ww + cx1)*DIM_] * (vx1*vy1);

            const float top = g00*(1.f-wx) + g01*wx;
            const float bot = g10*(1.f-wx) + g11*wx;
            acc += a * (top*(1.f-wy) + bot*wy);
        }
    }
    out[(size_t)bq*256 + h*32 + lane] = acc;
}

// ---------------- launch ----------------
extern "C" void kernel_launch(void* const* d_in, const int* in_sizes, int n_in,
                              void* d_out, int out_size)
{
    const float*   input  = (const float*)d_in[0];
    const float*   pos    = (const float*)d_in[1];
    const float*   refp   = (const float*)d_in[2];
    const float*   source = (const float*)d_in[3];
    // d_in[4] source_shape (int64), d_in[5] level_start (int64): compile-time constants
    const uint8_t* mask   = (const uint8_t*)d_in[6];
    const float*   ln1_g  = (const float*)d_in[7];
    const float*   ln1_b  = (const float*)d_in[8];
    const float*   ln2_g  = (const float*)d_in[9];
    const float*   ln2_b  = (const float*)d_in[10];
    const float*   Wv     = (const float*)d_in[11];
    const float*   bv     = (const float*)d_in[12];
    const float*   Woff   = (const float*)d_in[13];
    const float*   boff   = (const float*)d_in[14];
    const float*   Wattn  = (const float*)d_in[15];
    const float*   battn  = (const float*)d_in[16];
    const float*   Wout   = (const float*)d_in[17];
    const float*   bout   = (const float*)d_in[18];
    const float*   W1     = (const float*)d_in[19];
    const float*   b1     = (const float*)d_in[20];
    const float*   W2     = (const float*)d_in[21];
    const float*   b2     = (const float*)d_in[22];

    float* out_x   = (float*)d_out;
    float* out_loc = (float*)d_out + (size_t)BQ*DIM_;

    float *qp, *value, *off, *attn, *attnout, *xb, *yb, *ffn;
    cudaGetSymbolAddress((void**)&qp,      g_qp);
    cudaGetSymbolAddress((void**)&value,   g_value);
    cudaGetSymbolAddress((void**)&off,     g_off);
    cudaGetSymbolAddress((void**)&attn,    g_attn);
    cudaGetSymbolAddress((void**)&attnout, g_attnout);
    cudaGetSymbolAddress((void**)&xb,      g_x);
    cudaGetSymbolAddress((void**)&yb,      g_y);
    cudaGetSymbolAddress((void**)&ffn,     g_ffn);

    // 1) qp = LN1(input) + pos
    ln_kernel<<<BQ, 256>>>(input, ln1_g, ln1_b, pos, qp);

    // 2) value = mask-zero(source @ Wv + bv)
    {
        dim3 grid(DIM_/128, (MV + 127)/128);
        gemm_kernel<<<grid, 256>>>(source, Wv, bv, nullptr, mask, value, MV, DIM_, DIM_, 0);
    }
    // 3) offsets = qp @ Woff + boff
    {
        dim3 grid(DIM_/128, BQ/128);
        gemm_kernel<<<grid, 256>>>(qp, Woff, boff, nullptr, nullptr, off, BQ, DIM_, DIM_, 0);
    }
    // 4) attn logits = qp @ Wattn + battn
    {
        dim3 grid(128/128, BQ/128);
        gemm_kernel<<<grid, 256>>>(qp, Wattn, battn, nullptr, nullptr, attn, BQ, 128, DIM_, 0);
    }
    // 5) softmax over 16 points per head (in place)
    softmax_kernel<<<(BQ*NH + 255)/256, 256>>>(attn);

    // 6) loc = ref + off/normalizer  (written straight to output tail)
    loc_kernel<<<(BQ*256 + 255)/256, 256>>>(refp, off, out_loc);

    // 7) deformable sampling
    sample_kernel<<<BQ, 256>>>(value, out_loc, attn, attnout);

    // 8) x = input + attnout @ Wout + bout
    {
        dim3 grid(DIM_/128, BQ/128);
        gemm_kernel<<<grid, 256>>>(attnout, Wout, bout, input, nullptr, xb, BQ, DIM_, DIM_, 0);
    }
    // 9) y = LN2(x)
    ln_kernel<<<BQ, 256>>>(xb, ln2_g, ln2_b, nullptr, yb);

    // 10) ffn = relu(y @ W1 + b1)
    {
        dim3 grid(DFF/128, BQ/128);
        gemm_kernel<<<grid, 256>>>(yb, W1, b1, nullptr, nullptr, ffn, BQ, DFF, DIM_, 1);
    }
    // 11) out_x = x + ffn @ W2 + b2
    {
        dim3 grid(DIM_/128, BQ/128);
        gemm_kernel<<<grid, 256>>>(ffn, W2, b2, xb, nullptr, out_x, BQ, DIM_, DFF, 0);
    }
}

// round 2
// speedup vs baseline: 1.8817x; 1.8817x over previous
#include <cuda_runtime.h>
#include <cstdint>

#define B_      8
#define Q_      2048
#define DIM_    256
#define NH      8
#define HD      32
#define DFF     1024
#define LEN_IN_ 13294
#define BQ      (B_*Q_)
#define MV      (B_*LEN_IN_)   // 106352 rows of the value GEMM

// ---------------- scratch (static device arrays; no allocation) ----------------
__device__ float g_qp[BQ*DIM_];            // LN1(input)+pos
__device__ float g_value[MV*DIM_];         // source @ Wv + bv   (109 MB)
__device__ float g_off[BQ*DIM_];           // offset projections
__device__ float g_attn[BQ*128];           // attn logits -> probs (in place)
__device__ float g_attnout[BQ*DIM_];       // sampled attention output
__device__ float g_x[BQ*DIM_];             // residual 1
__device__ float g_y[BQ*DIM_];             // LN2 output
__device__ float g_ffn[BQ*DFF];            // FFN hidden

// ---------------- LayerNorm (+ optional additive term) ----------------
__global__ __launch_bounds__(256) void ln_kernel(
    const float* __restrict__ x, const float* __restrict__ g,
    const float* __restrict__ b, const float* __restrict__ addend,
    float* __restrict__ out)
{
    __shared__ float sbuf[8];
    const int row = blockIdx.x;
    const int t = threadIdx.x;
    const float v = x[(size_t)row*DIM_ + t];

    float s = v;
    #pragma unroll
    for (int o = 16; o; o >>= 1) s += __shfl_xor_sync(0xffffffffu, s, o);
    if ((t & 31) == 0) sbuf[t >> 5] = s;
    __syncthreads();
    float mean = 0.f;
    #pragma unroll
    for (int i = 0; i < 8; i++) mean += sbuf[i];
    mean *= (1.f/256.f);

    const float d = v - mean;
    float s2 = d*d;
    #pragma unroll
    for (int o = 16; o; o >>= 1) s2 += __shfl_xor_sync(0xffffffffu, s2, o);
    __syncthreads();
    if ((t & 31) == 0) sbuf[t >> 5] = s2;
    __syncthreads();
    float var = 0.f;
    #pragma unroll
    for (int i = 0; i < 8; i++) var += sbuf[i];
    var *= (1.f/256.f);

    float r = d * rsqrtf(var + 1e-5f) * g[t] + b[t];
    if (addend) r += addend[(size_t)row*DIM_ + t];
    out[(size_t)row*DIM_ + t] = r;
}

// ---------------- tf32 -> helpers ----------------
__device__ __forceinline__ uint32_t f2tf32(float f) {
    uint32_t u;
    asm("cvt.rna.tf32.f32 %0, %1;" : "=r"(u) : "f"(f));
    return u;
}

__device__ __forceinline__ void mma_tf32(float c[4], const uint32_t a[4], const uint32_t b[2]) {
    asm("mma.sync.aligned.m16n8k8.row.col.f32.tf32.tf32.f32 "
        "{%0,%1,%2,%3}, {%4,%5,%6,%7}, {%8,%9}, {%0,%1,%2,%3};"
        : "+f"(c[0]), "+f"(c[1]), "+f"(c[2]), "+f"(c[3])
        : "r"(a[0]), "r"(a[1]), "r"(a[2]), "r"(a[3]), "r"(b[0]), "r"(b[1]));
}

// ---------------- TF32 tensor-core GEMM: C = act(A@B + bias) [+resid] [mask rows] ----
// A: [M,K] row-major, B: [K,N] row-major. N % 128 == 0, K % 32 == 0. M guarded.
// Block tile 128x128, K-tile 32, 8 warps (2 M x 4 N), warp tile 64x32.
#define ASTR 36
#define BSTR 136
__global__ __launch_bounds__(256) void gemm_tc(
    const float* __restrict__ A, const float* __restrict__ Bm,
    const float* __restrict__ bias, const float* __restrict__ resid,
    const uint8_t* __restrict__ mask, float* __restrict__ C,
    int M, int N, int K, int relu)
{
    __shared__ __align__(16) uint32_t As[128][ASTR];  // [row][k]
    __shared__ __align__(16) uint32_t Bs[32][BSTR];   // [k][n]

    const int tid   = threadIdx.x;
    const int warp  = tid >> 5;
    const int lane  = tid & 31;
    const int gid   = lane >> 2;     // 0..7
    const int tig   = lane & 3;      // 0..3
    const int warpM = warp & 1;      // 2 warps over M
    const int warpN = warp >> 1;     // 4 warps over N
    const int row0  = blockIdx.y * 128;
    const int col0  = blockIdx.x * 128;

    // global load slots
    const int a_row = tid >> 1;            // 0..127
    const int a_col = (tid & 1) << 4;      // 0 or 16: thread covers cols [a_col, a_col+16) via 4 float4
    const int b_row = tid >> 3;            // 0..31
    const int b_col = (tid & 7) << 4;      // 0..112 step 16

    float acc[4][4][4];
    #pragma unroll
    for (int i = 0; i < 4; i++)
        #pragma unroll
        for (int j = 0; j < 4; j++)
            #pragma unroll
            for (int r = 0; r < 4; r++) acc[i][j][r] = 0.f;

    float4 ra[4], rb[4];
    const int nkt = K >> 5;

    // prefetch tile 0
    {
        const float* ap = A + (size_t)(row0 + a_row) * K + a_col;
        const bool av = (row0 + a_row) < M;
        #pragma unroll
        for (int i = 0; i < 4; i++)
            ra[i] = av ? *(const float4*)(ap + i*4) : make_float4(0.f,0.f,0.f,0.f);
        const float* bp = Bm + (size_t)b_row * N + col0 + b_col;
        #pragma unroll
        for (int i = 0; i < 4; i++)
            rb[i] = *(const float4*)(bp + i*4);
    }

    for (int t = 0; t < nkt; t++) {
        // STS (with tf32 convert)
        #pragma unroll
        for (int i = 0; i < 4; i++) {
            uint32_t* d = &As[a_row][a_col + i*4];
            d[0] = f2tf32(ra[i].x); d[1] = f2tf32(ra[i].y);
            d[2] = f2tf32(ra[i].z); d[3] = f2tf32(ra[i].w);
        }
        #pragma unroll
        for (int i = 0; i < 4; i++) {
            uint32_t* d = &Bs[b_row][b_col + i*4];
            d[0] = f2tf32(rb[i].x); d[1] = f2tf32(rb[i].y);
            d[2] = f2tf32(rb[i].z); d[3] = f2tf32(rb[i].w);
        }
        __syncthreads();

        // prefetch next tile into regs (overlaps with compute below)
        if (t + 1 < nkt) {
            const int k0 = (t + 1) << 5;
            const float* ap = A + (size_t)(row0 + a_row) * K + k0 + a_col;
            const bool av = (row0 + a_row) < M;
            #pragma unroll
            for (int i = 0; i < 4; i++)
                ra[i] = av ? *(const float4*)(ap + i*4) : make_float4(0.f,0.f,0.f,0.f);
            const float* bp = Bm + (size_t)(k0 + b_row) * N + col0 + b_col;
            #pragma unroll
            for (int i = 0; i < 4; i++)
                rb[i] = *(const float4*)(bp + i*4);
        }

        // compute: 4 k-steps of 8
        #pragma unroll
        for (int kk = 0; kk < 4; kk++) {
            const int kb = kk << 3;
            uint32_t af[4][4], bf[4][2];
            #pragma unroll
            for (int mt = 0; mt < 4; mt++) {
                const int r = warpM*64 + mt*16 + gid;
                af[mt][0] = As[r    ][kb + tig];
                af[mt][1] = As[r + 8][kb + tig];
                af[mt][2] = As[r    ][kb + tig + 4];
                af[mt][3] = As[r + 8][kb + tig + 4];
            }
            #pragma unroll
            for (int nt = 0; nt < 4; nt++) {
                const int c = warpN*32 + nt*8 + gid;
                bf[nt][0] = Bs[kb + tig    ][c];
                bf[nt][1] = Bs[kb + tig + 4][c];
            }
            #pragma unroll
            for (int mt = 0; mt < 4; mt++)
                #pragma unroll
                for (int nt = 0; nt < 4; nt++)
                    mma_tf32(acc[mt][nt], af[mt], bf[nt]);
        }
        __syncthreads();
    }

    // epilogue
    #pragma unroll
    for (int mt = 0; mt < 4; mt++) {
        #pragma unroll
        for (int half = 0; half < 2; half++) {
            const int r = row0 + warpM*64 + mt*16 + gid + half*8;
            if (r >= M) continue;
            const float mz = (mask && mask[r]) ? 0.f : 1.f;
            #pragma unroll
            for (int nt = 0; nt < 4; nt++) {
                const int c = col0 + warpN*32 + nt*8 + 2*tig;
                float v0 = acc[mt][nt][half*2 + 0] + bias[c + 0];
                float v1 = acc[mt][nt][half*2 + 1] + bias[c + 1];
                if (relu) { v0 = fmaxf(v0, 0.f); v1 = fmaxf(v1, 0.f); }
                if (resid) {
                    const float* rp = resid + (size_t)r*N + c;
                    v0 += rp[0]; v1 += rp[1];
                }
                float2 vv = make_float2(v0*mz, v1*mz);
                *(float2*)(C + (size_t)r*N + c) = vv;
            }
        }
    }
}

// ---------------- softmax over 16 points per (b,q,head) ----------------
__global__ __launch_bounds__(256) void softmax_kernel(float* __restrict__ attn)
{
    const int i = blockIdx.x * blockDim.x + threadIdx.x;   // (bq*8 + h)
    if (i >= BQ*NH) return;
    float* p = attn + (size_t)i * 16;
    float m = p[0];
    #pragma unroll
    for (int k = 1; k < 16; k++) m = fmaxf(m, p[k]);
    float e[16]; float s = 0.f;
    #pragma unroll
    for (int k = 0; k < 16; k++) { e[k] = __expf(p[k] - m); s += e[k]; }
    const float inv = 1.f / s;
    #pragma unroll
    for (int k = 0; k < 16; k++) p[k] = e[k] * inv;
}

// ---------------- loc = ref + off / normalizer ----------------
__global__ __launch_bounds__(256) void loc_kernel(
    const float* __restrict__ ref, const float* __restrict__ off,
    float* __restrict__ loc)
{
    const int idx = blockIdx.x * blockDim.x + threadIdx.x;
    if (idx >= BQ*256) return;
    const int c  = idx & 1;
    const int l  = (idx >> 3) & 3;
    const int bq = idx >> 8;
    const float nd[4] = {100.f, 50.f, 25.f, 13.f};  // square levels: W == H
    const float r = ref[((size_t)bq*4 + l)*2 + c];
    loc[idx] = r + off[idx] / nd[l];
}

// ---------------- MS-deformable bilinear sampling ----------------
// block = one (b,q); warp = head; lane = head_dim channel.
__global__ __launch_bounds__(256) void sample_kernel(
    const float* __restrict__ value, const float* __restrict__ loc,
    const float* __restrict__ attn, float* __restrict__ out)
{
    const int bq   = blockIdx.x;
    const int h    = threadIdx.x >> 5;
    const int lane = threadIdx.x & 31;
    const int b    = bq >> 11;           // / Q_
    const float* locp = loc  + (size_t)bq*256 + h*32;
    const float* ap   = attn + (size_t)bq*128 + h*16;

    constexpr int LH[4] = {100, 50, 25, 13};
    constexpr int LS[4] = {0, 10000, 12500, 13125};

    float acc = 0.f;
    #pragma unroll
    for (int l = 0; l < 4; l++) {
        const int Hh = LH[l], Ww = LH[l];
        const float* vb = value + ((size_t)b*LEN_IN_ + LS[l])*DIM_ + h*32 + lane;
        #pragma unroll
        for (int p = 0; p < 4; p++) {
            const float lx = locp[(l*4 + p)*2 + 0];
            const float ly = locp[(l*4 + p)*2 + 1];
            const float a  = ap[l*4 + p];
            const float x = lx * (float)Ww - 0.5f;
            const float y = ly * (float)Hh - 0.5f;
            const float x0f = floorf(x), y0f = floorf(y);
            const float wx = x - x0f, wy = y - y0f;
            const int x0 = (int)x0f, y0 = (int)y0f;
            const int x1 = x0 + 1,  y1 = y0 + 1;

            const float vx0 = (x0 >= 0 && x0 < Ww) ? 1.f : 0.f;
            const float vx1 = (x1 >= 0 && x1 < Ww) ? 1.f : 0.f;
            const float vy0 = (y0 >= 0 && y0 < Hh) ? 1.f : 0.f;
            const float vy1 = (y1 >= 0 && y1 < Hh) ? 1.f : 0.f;
            const int cx0 = min(max(x0, 0), Ww-1);
            const int cx1 = min(max(x1, 0), Ww-1);
            const int cy0 = min(max(y0, 0), Hh-1);
            const int cy1 = min(max(y1, 0), Hh-1);

            const float g00 = vb[(size_t)(cy0*Ww + cx0)*DIM_] * (vx0*vy0);
            const float g01 = vb[(size_t)(cy0*Ww + cx1)*DIM_] * (vx1*vy0);
            const float g10 = vb[(size_t)(cy1*Ww + cx0)*DIM_] * (vx0*vy1);
            const float g11 = vb[(size_t)(cy1*Ww + cx1)*DIM_] * (vx1*vy1);

            const float top = g00*(1.f-wx) + g01*wx;
            const float bot = g10*(1.f-wx) + g11*wx;
            acc += a * (top*(1.f-wy) + bot*wy);
        }
    }
    out[(size_t)bq*256 + h*32 + lane] = acc;
}

// ---------------- launch ----------------
extern "C" void kernel_launch(void* const* d_in, const int* in_sizes, int n_in,
                              void* d_out, int out_size)
{
    const float*   input  = (const float*)d_in[0];
    const float*   pos    = (const float*)d_in[1];
    const float*   refp   = (const float*)d_in[2];
    const float*   source = (const float*)d_in[3];
    // d_in[4] source_shape (int64), d_in[5] level_start (int64): compile-time constants
    const uint8_t* mask   = (const uint8_t*)d_in[6];
    const float*   ln1_g  = (const float*)d_in[7];
    const float*   ln1_b  = (const float*)d_in[8];
    const float*   ln2_g  = (const float*)d_in[9];
    const float*   ln2_b  = (const float*)d_in[10];
    const float*   Wv     = (const float*)d_in[11];
    const float*   bv     = (const float*)d_in[12];
    const float*   Woff   = (const float*)d_in[13];
    const float*   boff   = (const float*)d_in[14];
    const float*   Wattn  = (const float*)d_in[15];
    const float*   battn  = (const float*)d_in[16];
    const float*   Wout   = (const float*)d_in[17];
    const float*   bout   = (const float*)d_in[18];
    const float*   W1     = (const float*)d_in[19];
    const float*   b1     = (const float*)d_in[20];
    const float*   W2     = (const float*)d_in[21];
    const float*   b2     = (const float*)d_in[22];

    float* out_x   = (float*)d_out;
    float* out_loc = (float*)d_out + (size_t)BQ*DIM_;

    float *qp, *value, *off, *attn, *attnout, *xb, *yb, *ffn;
    cudaGetSymbolAddress((void**)&qp,      g_qp);
    cudaGetSymbolAddress((void**)&value,   g_value);
    cudaGetSymbolAddress((void**)&off,     g_off);
    cudaGetSymbolAddress((void**)&attn,    g_attn);
    cudaGetSymbolAddress((void**)&attnout, g_attnout);
    cudaGetSymbolAddress((void**)&xb,      g_x);
    cudaGetSymbolAddress((void**)&yb,      g_y);
    cudaGetSymbolAddress((void**)&ffn,     g_ffn);

    // 1) qp = LN1(input) + pos
    ln_kernel<<<BQ, 256>>>(input, ln1_g, ln1_b, pos, qp);

    // 2) value = mask-zero(source @ Wv + bv)
    {
        dim3 grid(DIM_/128, (MV + 127)/128);
        gemm_tc<<<grid, 256>>>(source, Wv, bv, nullptr, mask, value, MV, DIM_, DIM_, 0);
    }
    // 3) offsets = qp @ Woff + boff
    {
        dim3 grid(DIM_/128, BQ/128);
        gemm_tc<<<grid, 256>>>(qp, Woff, boff, nullptr, nullptr, off, BQ, DIM_, DIM_, 0);
    }
    // 4) attn logits = qp @ Wattn + battn
    {
        dim3 grid(1, BQ/128);
        gemm_tc<<<grid, 256>>>(qp, Wattn, battn, nullptr, nullptr, attn, BQ, 128, DIM_, 0);
    }
    // 5) softmax over 16 points per head (in place)
    softmax_kernel<<<(BQ*NH + 255)/256, 256>>>(attn);

    // 6) loc = ref + off/normalizer  (written straight to output tail)
    loc_kernel<<<(BQ*256 + 255)/256, 256>>>(refp, off, out_loc);

    // 7) deformable sampling
    sample_kernel<<<BQ, 256>>>(value, out_loc, attn, attnout);

    // 8) x = input + attnout @ Wout + bout
    {
        dim3 grid(DIM_/128, BQ/128);
        gemm_tc<<<grid, 256>>>(attnout, Wout, bout, input, nullptr, xb, BQ, DIM_, DIM_, 0);
    }
    // 9) y = LN2(x)
    ln_kernel<<<BQ, 256>>>(xb, ln2_g, ln2_b, nullptr, yb);

    // 10) ffn = relu(y @ W1 + b1)
    {
        dim3 grid(DFF/128, BQ/128);
        gemm_tc<<<grid, 256>>>(yb, W1, b1, nullptr, nullptr, ffn, BQ, DFF, DIM_, 1);
    }
    // 11) out_x = x + ffn @ W2 + b2
    {
        dim3 grid(DIM_/128, BQ/128);
        gemm_tc<<<grid, 256>>>(ffn, W2, b2, xb, nullptr, out_x, BQ, DIM_, DFF, 0);
    }
}

// round 3
// speedup vs baseline: 2.0266x; 1.0770x over previous
#include <cuda_runtime.h>
#include <cstdint>

#define B_      8
#define Q_      2048
#define DIM_    256
#define NH      8
#define HD      32
#define DFF     1024
#define LEN_IN_ 13294
#define BQ      (B_*Q_)
#define MV      (B_*LEN_IN_)   // 106352 rows of the value GEMM

// ---------------- scratch (static device arrays; no allocation) ----------------
__device__ float g_qp[BQ*DIM_];            // LN1(input)+pos
__device__ float g_value[MV*DIM_];         // source @ Wv + bv   (109 MB)
__device__ float g_off[BQ*DIM_];           // offset projections
__device__ float g_attn[BQ*128];           // attn logits (softmax fused into sampler)
__device__ float g_attnout[BQ*DIM_];       // sampled attention output
__device__ float g_x[BQ*DIM_];             // residual 1
__device__ float g_y[BQ*DIM_];             // LN2 output
__device__ float g_ffn[BQ*DFF];            // FFN hidden

// ---------------- LayerNorm (+ optional additive term) ----------------
__global__ __launch_bounds__(256) void ln_kernel(
    const float* __restrict__ x, const float* __restrict__ g,
    const float* __restrict__ b, const float* __restrict__ addend,
    float* __restrict__ out)
{
    __shared__ float sbuf[8];
    const int row = blockIdx.x;
    const int t = threadIdx.x;
    const float v = x[(size_t)row*DIM_ + t];

    float s = v;
    #pragma unroll
    for (int o = 16; o; o >>= 1) s += __shfl_xor_sync(0xffffffffu, s, o);
    if ((t & 31) == 0) sbuf[t >> 5] = s;
    __syncthreads();
    float mean = 0.f;
    #pragma unroll
    for (int i = 0; i < 8; i++) mean += sbuf[i];
    mean *= (1.f/256.f);

    const float d = v - mean;
    float s2 = d*d;
    #pragma unroll
    for (int o = 16; o; o >>= 1) s2 += __shfl_xor_sync(0xffffffffu, s2, o);
    __syncthreads();
    if ((t & 31) == 0) sbuf[t >> 5] = s2;
    __syncthreads();
    float var = 0.f;
    #pragma unroll
    for (int i = 0; i < 8; i++) var += sbuf[i];
    var *= (1.f/256.f);

    float r = d * rsqrtf(var + 1e-5f) * g[t] + b[t];
    if (addend) r += addend[(size_t)row*DIM_ + t];
    out[(size_t)row*DIM_ + t] = r;
}

// ---------------- tf32 helpers ----------------
__device__ __forceinline__ uint32_t f2tf32(float f) {
    uint32_t u;
    asm("cvt.rna.tf32.f32 %0, %1;" : "=r"(u) : "f"(f));
    return u;
}

__device__ __forceinline__ void mma_tf32(float c[4], const uint32_t a[4], const uint32_t b[2]) {
    asm("mma.sync.aligned.m16n8k8.row.col.f32.tf32.tf32.f32 "
        "{%0,%1,%2,%3}, {%4,%5,%6,%7}, {%8,%9}, {%0,%1,%2,%3};"
        : "+f"(c[0]), "+f"(c[1]), "+f"(c[2]), "+f"(c[3])
        : "r"(a[0]), "r"(a[1]), "r"(a[2]), "r"(a[3]), "r"(b[0]), "r"(b[1]));
}

__device__ __forceinline__ void cp_async16(void* smem_dst, const void* gsrc) {
    uint32_t s = (uint32_t)__cvta_generic_to_shared(smem_dst);
    asm volatile("cp.async.cg.shared.global [%0], [%1], 16;" :: "r"(s), "l"(gsrc));
}
__device__ __forceinline__ void cp_commit() { asm volatile("cp.async.commit_group;"); }
__device__ __forceinline__ void cp_wait0()  { asm volatile("cp.async.wait_group 0;"); }

// ---------------- TF32 tensor-core GEMM (2-stage pipelined) ----------------
// C = act(A@B + bias) [+resid] [mask rows]
// A: [M,K] row-major, B: [K,N] row-major. N % 128 == 0, K % 32 == 0. M guarded.
// Block tile 128x128, K-tile 32, 8 warps (2 M x 4 N), warp tile 64x32.
// A: register prefetch -> fragment-permuted smem (v4 LDS). B: cp.async, raw
// fp32 bits fed to MMA (HW tf32 truncation).
#define A_STAGE 4096                   // uint32 per stage (4 kk * 8 mrow * 32 lane * 4)
#define B_STR   136                    // padded row stride (floats)
#define B_STAGE (32*B_STR)             // floats per stage
#define GEMM_SMEM_BYTES ((2*A_STAGE + 2*B_STAGE) * 4)

__global__ __launch_bounds__(256, 2) void gemm_tc(
    const float* __restrict__ A, const float* __restrict__ Bm,
    const float* __restrict__ bias, const float* __restrict__ resid,
    const uint8_t* __restrict__ mask, float* __restrict__ C,
    int M, int N, int K, int relu)
{
    extern __shared__ float dynsmem[];
    uint32_t* AsF = (uint32_t*)dynsmem;          // [2][A_STAGE]
    float*    BsS = dynsmem + 2*A_STAGE;         // [2][32][B_STR]

    const int tid   = threadIdx.x;
    const int warp  = tid >> 5;
    const int lane  = tid & 31;
    const int gid   = lane >> 2;     // 0..7
    const int tig   = lane & 3;      // 0..3
    const int warpM = warp & 1;      // 2 warps over M
    const int warpN = warp >> 1;     // 4 warps over N
    const int row0  = blockIdx.y * 128;
    const int col0  = blockIdx.x * 128;

    // A global-load slot: 16 floats per thread (row a_row, k in [a_col, a_col+16))
    const int a_row = tid >> 1;
    const int a_col = (tid & 1) << 4;
    const bool avalid = (row0 + a_row) < M;
    const float* aptr = A + (size_t)(row0 + a_row) * K + a_col;

    // precompute A fragment-permute destination bases
    // dest idx = (kk*8 + mrow)*128 + ((a_row&7)*4 + (k&3))*4 + ((k>>2)&1)*2 + ((a_row>>3)&1)
    const int a_mrow = a_row >> 4;
    const int a_hm   = (a_row >> 3) & 1;
    const int a_within = (a_row & 7) << 2;

    float acc[4][4][4];
    #pragma unroll
    for (int i = 0; i < 4; i++)
        #pragma unroll
        for (int j = 0; j < 4; j++)
            #pragma unroll
            for (int r = 0; r < 4; r++) acc[i][j][r] = 0.f;

    const int nkt = K >> 5;
    float4 ra[4];

    // ---- prologue: A(0) -> regs, B(0) -> cp.async stage 0 ----
    #pragma unroll
    for (int i = 0; i < 4; i++)
        ra[i] = avalid ? *(const float4*)(aptr + i*4) : make_float4(0.f,0.f,0.f,0.f);
    #pragma unroll
    for (int i = 0; i < 4; i++) {
        const int chunk = i*256 + tid;
        const int br = chunk >> 5;
        const int bn = (chunk & 31) << 2;
        cp_async16(&BsS[br*B_STR + bn], Bm + (size_t)br*N + col0 + bn);
    }
    cp_commit();

    // STS A(0) into stage 0 (fragment-permuted, tf32-rounded)
    {
        uint32_t* dst = AsF;
        #pragma unroll
        for (int i = 0; i < 4; i++) {
            float v[4] = {ra[i].x, ra[i].y, ra[i].z, ra[i].w};
            #pragma unroll
            for (int j = 0; j < 4; j++) {
                const int k  = a_col + i*4 + j;
                const int kk = k >> 3;
                const int idx = ((kk*8 + a_mrow) << 7) + ((a_within + (k & 3)) << 2)
                              + (((k >> 2) & 1) << 1) + a_hm;
                dst[idx] = f2tf32(v[j]);
            }
        }
    }

    for (int t = 0; t < nkt; t++) {
        const int p = t & 1;
        cp_wait0();
        __syncthreads();

        const bool more = (t + 1) < nkt;
        if (more) {
            const int k0n = (t + 1) << 5;
            #pragma unroll
            for (int i = 0; i < 4; i++)
                ra[i] = avalid ? *(const float4*)(aptr + k0n + i*4)
                               : make_float4(0.f,0.f,0.f,0.f);
            float* bdst = BsS + (p ^ 1) * B_STAGE;
            #pragma unroll
            for (int i = 0; i < 4; i++) {
                const int chunk = i*256 + tid;
                const int br = chunk >> 5;
                const int bn = (chunk & 31) << 2;
                cp_async16(&bdst[br*B_STR + bn], Bm + (size_t)(k0n + br)*N + col0 + bn);
            }
            cp_commit();
        }

        // ---- compute stage p ----
        const uint32_t* ab = AsF + p * A_STAGE;
        const float*    bb = BsS + p * B_STAGE;
        #pragma unroll
        for (int kk = 0; kk < 4; kk++) {
            uint32_t af[4][4];
            #pragma unroll
            for (int mt = 0; mt < 4; mt++) {
                const uint4 v = *(const uint4*)&ab[((kk*8 + warpM*4 + mt) << 7) + (lane << 2)];
                af[mt][0] = v.x; af[mt][1] = v.y; af[mt][2] = v.z; af[mt][3] = v.w;
            }
            uint32_t bf[4][2];
            #pragma unroll
            for (int nt = 0; nt < 4; nt++) {
                const int c = warpN*32 + nt*8 + gid;
                bf[nt][0] = __float_as_uint(bb[(kk*8 + tig    )*B_STR + c]);
                bf[nt][1] = __float_as_uint(bb[(kk*8 + tig + 4)*B_STR + c]);
            }
            #pragma unroll
            for (int mt = 0; mt < 4; mt++)
                #pragma unroll
                for (int nt = 0; nt < 4; nt++)
                    mma_tf32(acc[mt][nt], af[mt], bf[nt]);
        }

        // ---- STS A(t+1) into other stage ----
        if (more) {
            uint32_t* dst = AsF + (p ^ 1) * A_STAGE;
            #pragma unroll
            for (int i = 0; i < 4; i++) {
                float v[4] = {ra[i].x, ra[i].y, ra[i].z, ra[i].w};
                #pragma unroll
                for (int j = 0; j < 4; j++) {
                    const int k  = a_col + i*4 + j;
                    const int kk = k >> 3;
                    const int idx = ((kk*8 + a_mrow) << 7) + ((a_within + (k & 3)) << 2)
                                  + (((k >> 2) & 1) << 1) + a_hm;
                    dst[idx] = f2tf32(v[j]);
                }
            }
        }
    }

    // ---- epilogue ----
    #pragma unroll
    for (int mt = 0; mt < 4; mt++) {
        #pragma unroll
        for (int half = 0; half < 2; half++) {
            const int r = row0 + warpM*64 + mt*16 + gid + half*8;
            if (r >= M) continue;
            const float mz = (mask && mask[r]) ? 0.f : 1.f;
            #pragma unroll
            for (int nt = 0; nt < 4; nt++) {
                const int c = col0 + warpN*32 + nt*8 + 2*tig;
                float v0 = acc[mt][nt][half*2 + 0] + bias[c + 0];
                float v1 = acc[mt][nt][half*2 + 1] + bias[c + 1];
                if (relu) { v0 = fmaxf(v0, 0.f); v1 = fmaxf(v1, 0.f); }
                if (resid) {
                    const float* rp = resid + (size_t)r*N + c;
                    v0 += rp[0]; v1 += rp[1];
                }
                float2 vv = make_float2(v0*mz, v1*mz);
                *(float2*)(C + (size_t)r*N + c) = vv;
            }
        }
    }
}

// ---------------- fused loc + softmax + MS-deformable bilinear sampling ----------------
// block = one (b,q); warp = head; lane = head_dim channel.
__global__ __launch_bounds__(256) void sample_kernel(
    const float* __restrict__ value, const float* __restrict__ off,
    const float* __restrict__ attnlog, const float* __restrict__ ref,
    float* __restrict__ out_loc, float* __restrict__ out)
{
    __shared__ float s_loc[256];
    __shared__ float s_attn[128];

    const int bq   = blockIdx.x;
    const int tid  = threadIdx.x;
    const int h    = tid >> 5;
    const int lane = tid & 31;
    const int b    = bq >> 11;           // / Q_

    // loc = ref + off/normalizer (also stream to output)
    {
        const int c = tid & 1;
        const int l = (tid >> 3) & 3;
        const float nd[4] = {100.f, 50.f, 25.f, 13.f};
        const float v = ref[((size_t)bq*4 + l)*2 + c]
                      + off[(size_t)bq*256 + tid] / nd[l];
        s_loc[tid] = v;
        out_loc[(size_t)bq*256 + tid] = v;
    }
    // softmax over 16 points per head (16-lane segments of warps 0..3)
    if (tid < 128) {
        const float logit = attnlog[(size_t)bq*128 + tid];
        float m = logit;
        #pragma unroll
        for (int o = 8; o; o >>= 1) m = fmaxf(m, __shfl_xor_sync(0xffffffffu, m, o, 16));
        const float e = __expf(logit - m);
        float s = e;
        #pragma unroll
        for (int o = 8; o; o >>= 1) s += __shfl_xor_sync(0xffffffffu, s, o, 16);
        s_attn[tid] = e / s;
    }
    __syncthreads();

    const float* locp = s_loc  + h*32;
    const float* ap   = s_attn + h*16;

    constexpr int LH[4] = {100, 50, 25, 13};
    constexpr int LS[4] = {0, 10000, 12500, 13125};

    float acc = 0.f;
    #pragma unroll
    for (int l = 0; l < 4; l++) {
        const int Hh = LH[l], Ww = LH[l];
        const float* vb = value + ((size_t)b*LEN_IN_ + LS[l])*DIM_ + h*32 + lane;
        #pragma unroll
        for (int p = 0; p < 4; p++) {
            const float lx = locp[(l*4 + p)*2 + 0];
            const float ly = locp[(l*4 + p)*2 + 1];
            const float a  = ap[l*4 + p];
            const float x = lx * (float)Ww - 0.5f;
            const float y = ly * (float)Hh - 0.5f;
            const float x0f = floorf(x), y0f = floorf(y);
            const float wx = x - x0f, wy = y - y0f;
            const int x0 = (int)x0f, y0 = (int)y0f;
            const int x1 = x0 + 1,  y1 = y0 + 1;

            const float vx0 = (x0 >= 0 && x0 < Ww) ? 1.f : 0.f;
            const float vx1 = (x1 >= 0 && x1 < Ww) ? 1.f : 0.f;
            const float vy0 = (y0 >= 0 && y0 < Hh) ? 1.f : 0.f;
            const float vy1 = (y1 >= 0 && y1 < Hh) ? 1.f : 0.f;
            const int cx0 = min(max(x0, 0), Ww-1);
            const int cx1 = min(max(x1, 0), Ww-1);
            const int cy0 = min(max(y0, 0), Hh-1);
            const int cy1 = min(max(y1, 0), Hh-1);

            const float g00 = vb[(size_t)(cy0*Ww + cx0)*DIM_] * (vx0*vy0);
            const float g01 = vb[(size_t)(cy0*Ww + cx1)*DIM_] * (vx1*vy0);
            const float g10 = vb[(size_t)(cy1*Ww + cx0)*DIM_] * (vx0*vy1);
            const float g11 = vb[(size_t)(cy1*Ww + cx1)*DIM_] * (vx1*vy1);

            const float top = g00*(1.f-wx) + g01*wx;
            const float bot = g10*(1.f-wx) + g11*wx;
            acc += a * (top*(1.f-wy) + bot*wy);
        }
    }
    out[(size_t)bq*256 + h*32 + lane] = acc;
}

// ---------------- launch ----------------
extern "C" void kernel_launch(void* const* d_in, const int* in_sizes, int n_in,
                              void* d_out, int out_size)
{
    const float*   input  = (const float*)d_in[0];
    const float*   pos    = (const float*)d_in[1];
    const float*   refp   = (const float*)d_in[2];
    const float*   source = (const float*)d_in[3];
    // d_in[4] source_shape (int64), d_in[5] level_start (int64): compile-time constants
    const uint8_t* mask   = (const uint8_t*)d_in[6];
    const float*   ln1_g  = (const float*)d_in[7];
    const float*   ln1_b  = (const float*)d_in[8];
    const float*   ln2_g  = (const float*)d_in[9];
    const float*   ln2_b  = (const float*)d_in[10];
    const float*   Wv     = (const float*)d_in[11];
    const float*   bv     = (const float*)d_in[12];
    const float*   Woff   = (const float*)d_in[13];
    const float*   boff   = (const float*)d_in[14];
    const float*   Wattn  = (const float*)d_in[15];
    const float*   battn  = (const float*)d_in[16];
    const float*   Wout   = (const float*)d_in[17];
    const float*   bout   = (const float*)d_in[18];
    const float*   W1     = (const float*)d_in[19];
    const float*   b1     = (const float*)d_in[20];
    const float*   W2     = (const float*)d_in[21];
    const float*   b2     = (const float*)d_in[22];

    float* out_x   = (float*)d_out;
    float* out_loc = (float*)d_out + (size_t)BQ*DIM_;

    float *qp, *value, *off, *attn, *attnout, *xb, *yb, *ffn;
    cudaGetSymbolAddress((void**)&qp,      g_qp);
    cudaGetSymbolAddress((void**)&value,   g_value);
    cudaGetSymbolAddress((void**)&off,     g_off);
    cudaGetSymbolAddress((void**)&attn,    g_attn);
    cudaGetSymbolAddress((void**)&attnout, g_attnout);
    cudaGetSymbolAddress((void**)&xb,      g_x);
    cudaGetSymbolAddress((void**)&yb,      g_y);
    cudaGetSymbolAddress((void**)&ffn,     g_ffn);

    cudaFuncSetAttribute(gemm_tc, cudaFuncAttributeMaxDynamicSharedMemorySize,
                         GEMM_SMEM_BYTES);

    // 1) qp = LN1(input) + pos
    ln_kernel<<<BQ, 256>>>(input, ln1_g, ln1_b, pos, qp);

    // 2) value = mask-zero(source @ Wv + bv)
    {
        dim3 grid(DIM_/128, (MV + 127)/128);
        gemm_tc<<<grid, 256, GEMM_SMEM_BYTES>>>(source, Wv, bv, nullptr, mask, value, MV, DIM_, DIM_, 0);
    }
    // 3) offsets = qp @ Woff + boff
    {
        dim3 grid(DIM_/128, BQ/128);
        gemm_tc<<<grid, 256, GEMM_SMEM_BYTES>>>(qp, Woff, boff, nullptr, nullptr, off, BQ, DIM_, DIM_, 0);
    }
    // 4) attn logits = qp @ Wattn + battn
    {
        dim3 grid(1, BQ/128);
        gemm_tc<<<grid, 256, GEMM_SMEM_BYTES>>>(qp, Wattn, battn, nullptr, nullptr, attn, BQ, 128, DIM_, 0);
    }
    // 5) fused loc + softmax + deformable sampling (loc streamed to output)
    sample_kernel<<<BQ, 256>>>(value, off, attn, refp, out_loc, attnout);

    // 6) x = input + attnout @ Wout + bout
    {
        dim3 grid(DIM_/128, BQ/128);
        gemm_tc<<<grid, 256, GEMM_SMEM_BYTES>>>(attnout, Wout, bout, input, nullptr, xb, BQ, DIM_, DIM_, 0);
    }
    // 7) y = LN2(x)
    ln_kernel<<<BQ, 256>>>(xb, ln2_g, ln2_b, nullptr, yb);

    // 8) ffn = relu(y @ W1 + b1)
    {
        dim3 grid(DFF/128, BQ/128);
        gemm_tc<<<grid, 256, GEMM_SMEM_BYTES>>>(yb, W1, b1, nullptr, nullptr, ffn, BQ, DFF, DIM_, 1);
    }
    // 9) out_x = x + ffn @ W2 + b2
    {
        dim3 grid(DIM_/128, BQ/128);
        gemm_tc<<<grid, 256, GEMM_SMEM_BYTES>>>(ffn, W2, b2, xb, nullptr, out_x, BQ, DIM_, DFF, 0);
    }
}